// round 1
// baseline (speedup 1.0000x reference)
#include <cuda_runtime.h>

// Problem constants
#define BATCH   4
#define NPTS    16384
#define HALF    8192
#define FDIM    32
#define SPLITS  4
#define CAND    (HALF / SPLITS)      // 2048 candidates per split
#define QTHREADS 256

// Output layout (concatenated tuple, float32):
//   valid_pc   : BATCH*HALF*3   at 0
//   valid_feats: BATCH*HALF*32  at OFF_VFEAT
//   n_idx      : BATCH*HALF     at OFF_NIDX
//   rnds       : NPTS           at OFF_RNDS
#define OFF_VPC   0
#define OFF_VFEAT (BATCH * HALF * 3)                  // 98304
#define OFF_NIDX  (OFF_VFEAT + BATCH * HALF * FDIM)   // 1146880
#define OFF_RNDS  (OFF_NIDX + BATCH * HALF)           // 1179648

// Scratch (device globals; no allocation allowed)
__device__ float4 g_valid[BATCH][HALF];          // (2x, 2y, 2z, p2)
__device__ float4 g_query[BATCH][HALF];          // (x, y, z, q2)
__device__ float4 g_part[BATCH][SPLITS][HALF];   // (d1, d2, bits(i1), bits(i2))

// ||v||^2 with left-to-right adds, no FMA contraction (match jax fp32 semantics)
__device__ __forceinline__ float sq3(float x, float y, float z) {
    return __fadd_rn(__fadd_rn(__fmul_rn(x, x), __fmul_rn(y, y)), __fmul_rn(z, z));
}

// ---------------------------------------------------------------------------
// Kernel 1: gathers. One grid-stride-free launch covering all copy work:
//   [0, WF)          : valid_feats as float4 (coalesced writes)
//   [WF, WF+WP)      : valid_pc -> out + scratch (scaled coords + p2)
//   [.., +WP)        : invalid_pc -> query scratch (coords + q2)
//   [.., +NPTS)      : rnds -> out (as float)
// ---------------------------------------------------------------------------
__global__ void gather_kernel(const float* __restrict__ pc,
                              const float4* __restrict__ feats4,
                              const int* __restrict__ rnds,
                              float* __restrict__ out) {
    int i = blockIdx.x * blockDim.x + threadIdx.x;

    const int WF = BATCH * HALF * 8;   // feats in float4 units (32 floats = 8 float4)
    const int WP = BATCH * HALF;

    if (i < WF) {
        int c = i & 7;
        int t = (i >> 3) & (HALF - 1);
        int b = i >> 16;                  // i / (HALF*8)
        int v = rnds[t];
        float4 val = feats4[(b * NPTS + v) * 8 + c];
        ((float4*)(out + OFF_VFEAT))[(b * HALF + t) * 8 + c] = val;
        return;
    }
    i -= WF;
    if (i < WP) {
        int t = i & (HALF - 1);
        int b = i >> 13;
        int v = rnds[t];
        int base = (b * NPTS + v) * 3;
        float x = pc[base + 0];
        float y = pc[base + 1];
        float z = pc[base + 2];
        int ob = OFF_VPC + (b * HALF + t) * 3;
        out[ob + 0] = x;
        out[ob + 1] = y;
        out[ob + 2] = z;
        // 2*x is exact in fp32 -> dot(q, 2p) == 2*dot(q,p) bit-exactly
        g_valid[b][t] = make_float4(2.0f * x, 2.0f * y, 2.0f * z, sq3(x, y, z));
        return;
    }
    i -= WP;
    if (i < WP) {
        int t = i & (HALF - 1);
        int b = i >> 13;
        int v = rnds[HALF + t];
        int base = (b * NPTS + v) * 3;
        float x = pc[base + 0];
        float y = pc[base + 1];
        float z = pc[base + 2];
        g_query[b][t] = make_float4(x, y, z, sq3(x, y, z));
        return;
    }
    i -= WP;
    if (i < NPTS) {
        out[OFF_RNDS + i] = (float)rnds[i];
    }
}

// ---------------------------------------------------------------------------
// Kernel 2: brute-force top-2 over a 2048-candidate split.
// grid = (HALF/QTHREADS, SPLITS, BATCH); 32KB static smem per block.
// Each thread owns one query; broadcast LDS.128 per candidate.
// d2 = (q2 + p2) - 2*dot, matching reference formula & rounding (no FMA).
// Strict '<' preserves stable (lowest-index-first) tie-break of jax top_k.
// ---------------------------------------------------------------------------
__global__ void __launch_bounds__(QTHREADS) knn_kernel() {
    __shared__ float4 sm[CAND];

    const int b = blockIdx.z;
    const int s = blockIdx.y;
    const int q = blockIdx.x * QTHREADS + threadIdx.x;

    const float4* src = &g_valid[b][s * CAND];
    for (int i = threadIdx.x; i < CAND; i += QTHREADS) sm[i] = src[i];
    __syncthreads();

    float4 Q = g_query[b][q];
    const float qx = Q.x, qy = Q.y, qz = Q.z, q2 = Q.w;

    const float INF = __int_as_float(0x7f800000);
    float best1 = INF, best2 = INF;
    int i1 = 0, i2 = 0;

#pragma unroll 8
    for (int j = 0; j < CAND; ++j) {
        float4 p = sm[j];
        // dot2 == 2*dot(q, p_orig), exact
        float dot2 = __fadd_rn(__fadd_rn(__fmul_rn(qx, p.x), __fmul_rn(qy, p.y)),
                               __fmul_rn(qz, p.z));
        float d2 = __fsub_rn(__fadd_rn(q2, p.w), dot2);
        if (d2 < best1) {
            best2 = best1; i2 = i1;
            best1 = d2;    i1 = j;
        } else if (d2 < best2) {
            best2 = d2;    i2 = j;
        }
    }

    g_part[b][s][q] = make_float4(best1, best2,
                                  __int_as_float(s * CAND + i1),
                                  __int_as_float(s * CAND + i2));
}

// ---------------------------------------------------------------------------
// Kernel 3: merge SPLITS partial top-2 lists -> final 2nd-NN index.
// Comparator ties broken by smaller index (stable top_k semantics).
// ---------------------------------------------------------------------------
__global__ void merge_kernel(float* __restrict__ out) {
    int i = blockIdx.x * blockDim.x + threadIdx.x;
    if (i >= BATCH * HALF) return;
    int b = i >> 13;
    int q = i & (HALF - 1);

    const float INF = __int_as_float(0x7f800000);
    float bd1 = INF, bd2 = INF;
    int bi1 = 0x7fffffff, bi2 = 0x7fffffff;

#pragma unroll
    for (int s = 0; s < SPLITS; ++s) {
        float4 p = g_part[b][s][q];
        float d;
        int id;

        d = p.x; id = __float_as_int(p.z);
        if (d < bd1 || (d == bd1 && id < bi1)) {
            bd2 = bd1; bi2 = bi1; bd1 = d; bi1 = id;
        } else if (d < bd2 || (d == bd2 && id < bi2)) {
            bd2 = d; bi2 = id;
        }

        d = p.y; id = __float_as_int(p.w);
        if (d < bd1 || (d == bd1 && id < bi1)) {
            bd2 = bd1; bi2 = bi1; bd1 = d; bi1 = id;
        } else if (d < bd2 || (d == bd2 && id < bi2)) {
            bd2 = d; bi2 = id;
        }
    }

    out[OFF_NIDX + i] = (float)bi2;
}

// ---------------------------------------------------------------------------
extern "C" void kernel_launch(void* const* d_in, const int* in_sizes, int n_in,
                              void* d_out, int out_size) {
    const float*  pc    = (const float*)d_in[0];
    const float4* feats = (const float4*)d_in[1];
    const int*    rnds  = (const int*)d_in[2];
    float*        out   = (float*)d_out;

    (void)in_sizes; (void)n_in; (void)out_size;

    // Gather: WF + 2*WP + NPTS = 262144 + 65536 + 16384 = 344064 items
    const int total = BATCH * HALF * 8 + 2 * BATCH * HALF + NPTS;
    gather_kernel<<<(total + 255) / 256, 256>>>(pc, feats, rnds, out);

    dim3 grid(HALF / QTHREADS, SPLITS, BATCH);
    knn_kernel<<<grid, QTHREADS>>>();

    merge_kernel<<<(BATCH * HALF + 255) / 256, 256>>>(out);
}